// round 4
// baseline (speedup 1.0000x reference)
#include <cuda_runtime.h>
#include <cstdint>

#define COLS    16384
#define THREADS 512
#define V4      8                 // uint4 per thread (32 elements)
#define NBINS   2048              // 11-bit radix pass
#define CAP     2048
#define REGCAND 256
#define PIVOT0  0xC0000000u       // key_of(+2.0f), aligned to bin 1536 boundary

// Order-preserving float->uint transform: 2 ops (SHF + LOP3)
__device__ __forceinline__ unsigned key_of(unsigned u) {
    return u ^ (unsigned)(((int)u >> 31) | (int)0x80000000);
}
// Inverse: 3 ops (SHF + LOP3-fused not/or + XOR)
__device__ __forceinline__ float val_of(unsigned kx) {
    return __uint_as_float(kx ^ (unsigned)((~((int)kx >> 31)) | (int)0x80000000));
}

__global__ void __launch_bounds__(THREADS, 2)
topk_threshold_kernel(const float* __restrict__ x,
                      float* __restrict__ out,
                      const int* __restrict__ kptr)
{
    __shared__ unsigned hist[NBINS];    // 8 KB; reused as candidate buffer
    __shared__ unsigned wsum[16];
    __shared__ unsigned sh_bin, sh_krem, sh_bincnt, sh_cnt, sh_tkey, sh_c;
    unsigned* cand = hist;

    const int tid  = threadIdx.x;
    const int lane = tid & 31;
    const int wid  = tid >> 5;
    const size_t row_off = (size_t)blockIdx.x * COLS;
    const uint4* __restrict__ xin = (const uint4*)(x + row_off);
    float4* __restrict__ oout     = (float4*)(out + row_off);

    const unsigned k = kptr ? (unsigned)__ldg(kptr) : 64u;

    // ---- Phase 1a: batched loads (MLP=8), then transform in place ----
    uint4 kk[V4];
    #pragma unroll
    for (int i = 0; i < V4; i++) kk[i] = __ldcs(&xin[tid + i * THREADS]);
    #pragma unroll
    for (int i = 0; i < V4; i++) {
        kk[i].x = key_of(kk[i].x); kk[i].y = key_of(kk[i].y);
        kk[i].z = key_of(kk[i].z); kk[i].w = key_of(kk[i].w);
    }

    // ---- Phase 1b/2: pivoted histogram + bin select (exact; full-hist fallback) ----
    unsigned pivot = PIVOT0;
    unsigned binp, krem1, bincnt;

    for (;;) {
        #pragma unroll
        for (int b = tid; b < NBINS; b += THREADS) hist[b] = 0u;
        __syncthreads();

        // only elements >= pivot touch the histogram (~2% on the fast path)
        #pragma unroll
        for (int i = 0; i < V4; i++) {
            if (kk[i].x >= pivot) atomicAdd(&hist[kk[i].x >> 21], 1u);
            if (kk[i].y >= pivot) atomicAdd(&hist[kk[i].y >> 21], 1u);
            if (kk[i].z >= pivot) atomicAdd(&hist[kk[i].z >> 21], 1u);
            if (kk[i].w >= pivot) atomicAdd(&hist[kk[i].w >> 21], 1u);
        }
        __syncthreads();

        // block suffix-sum over 2048 bins (4 bins/thread)
        unsigned gs = hist[tid * 4 + 0] + hist[tid * 4 + 1]
                    + hist[tid * 4 + 2] + hist[tid * 4 + 3];
        unsigned s = gs;
        #pragma unroll
        for (int off = 1; off < 32; off <<= 1) {
            unsigned v = __shfl_down_sync(0xFFFFFFFFu, s, off);
            if (lane + off < 32) s += v;
        }
        if (lane == 0) wsum[wid] = s;
        __syncthreads();

        unsigned total = 0, woff = 0;
        #pragma unroll
        for (int w = 0; w < 16; w++) {
            total += wsum[w];
            if (w > wid) woff += wsum[w];
        }
        unsigned ssum = s + woff;   // count in bins >= my group

        if (total >= k) {           // pivot kept at least k elements -> exact
            if (ssum >= k && (ssum - gs) < k) {
                unsigned above = ssum - gs;
                int b = 0;
                #pragma unroll
                for (int bb = 3; bb >= 0; bb--) {
                    unsigned c = hist[tid * 4 + bb];
                    if (above + c >= k) { b = bb; break; }
                    above += c;
                }
                sh_bin    = (unsigned)(tid * 4 + b);
                sh_krem   = k - above;
                sh_bincnt = hist[tid * 4 + b];
                sh_cnt    = 0u;
            }
            __syncthreads();
            binp = sh_bin; krem1 = sh_krem; bincnt = sh_bincnt;
            break;
        }
        // fallback: pivot cut too deep (never for Gaussian) -> full histogram
        pivot = 0u;
        __syncthreads();
    }

    if (bincnt <= CAP) {
        // ---- Phase 3a: compact tie-bin candidates from registers ----
        #pragma unroll
        for (int i = 0; i < V4; i++) {
            #pragma unroll
            for (int j = 0; j < 4; j++) {
                unsigned ky = ((const unsigned*)&kk[i])[j];
                if ((ky >> 21) == binp) {
                    unsigned p = atomicAdd(&sh_cnt, 1u);
                    cand[p] = ky;
                }
            }
        }
        __syncthreads();

        // ---- Phase 3b: warp 0 refines remaining 21 bits ----
        if (wid == 0) {
            const int n = (int)sh_cnt;
            unsigned krem = krem1;
            unsigned cur  = 0u;
            if (n <= REGCAND) {
                unsigned c[8];
                #pragma unroll
                for (int j = 0; j < 8; j++)
                    c[j] = (lane + 32 * j < n) ? cand[lane + 32 * j] : 0u;
                for (int bit = 20; bit >= 0; bit--) {
                    unsigned want = (cur << 1) | 1u;
                    unsigned mask = (1u << (21 - bit)) - 1u;
                    unsigned cnt = 0;
                    #pragma unroll
                    for (int j = 0; j < 8; j++)
                        cnt += (((c[j] >> bit) & mask) == want);
                    cnt = __reduce_add_sync(0xFFFFFFFFu, cnt);
                    if (cnt >= krem) cur = want;
                    else { cur = want - 1u; krem -= cnt; }
                }
            } else {
                for (int bit = 20; bit >= 0; bit--) {
                    unsigned want = (cur << 1) | 1u;
                    unsigned mask = (1u << (21 - bit)) - 1u;
                    unsigned cnt = 0;
                    for (int i = lane; i < n; i += 32)
                        cnt += (((cand[i] >> bit) & mask) == want);
                    cnt = __reduce_add_sync(0xFFFFFFFFu, cnt);
                    if (cnt >= krem) cur = want;
                    else { cur = want - 1u; krem -= cnt; }
                }
            }
            if (lane == 0) sh_tkey = (binp << 21) | cur;
        }
        __syncthreads();
    } else {
        // ---- Fallback (pathological tie bin): block-wide bitwise select ----
        unsigned krem = krem1;
        unsigned cur  = 0u;
        for (int bit = 20; bit >= 0; bit--) {
            if (tid == 0) sh_c = 0u;
            __syncthreads();
            unsigned want  = (cur << 1) | 1u;
            unsigned fullw = (binp << (21 - bit)) | want;
            unsigned local = 0;
            #pragma unroll
            for (int i = 0; i < V4; i++) {
                local += ((kk[i].x >> bit) == fullw);
                local += ((kk[i].y >> bit) == fullw);
                local += ((kk[i].z >> bit) == fullw);
                local += ((kk[i].w >> bit) == fullw);
            }
            local = __reduce_add_sync(0xFFFFFFFFu, local);
            if (lane == 0) atomicAdd(&sh_c, local);
            __syncthreads();
            unsigned cnt = sh_c;
            if (cnt >= krem) cur = want;
            else { cur = want - 1u; krem -= cnt; }
            __syncthreads();
        }
        if (tid == 0) sh_tkey = (binp << 21) | cur;
        __syncthreads();
    }

    const unsigned tkey = sh_tkey;

    // ---- Phase 4: stream output straight from registers ----
    #pragma unroll
    for (int i = 0; i < V4; i++) {
        float4 o;
        o.x = (kk[i].x >= tkey) ? val_of(kk[i].x) : 0.0f;
        o.y = (kk[i].y >= tkey) ? val_of(kk[i].y) : 0.0f;
        o.z = (kk[i].z >= tkey) ? val_of(kk[i].z) : 0.0f;
        o.w = (kk[i].w >= tkey) ? val_of(kk[i].w) : 0.0f;
        __stcs(&oout[tid + i * THREADS], o);
    }
}

extern "C" void kernel_launch(void* const* d_in, const int* in_sizes, int n_in,
                              void* d_out, int out_size) {
    const float* x  = (const float*)d_in[0];
    const int* kptr = (n_in > 1) ? (const int*)d_in[1] : nullptr;
    const int rows  = in_sizes[0] / COLS;
    topk_threshold_kernel<<<rows, THREADS>>>(x, (float*)d_out, kptr);
}

// round 5
// speedup vs baseline: 1.1197x; 1.1197x over previous
#include <cuda_runtime.h>
#include <cstdint>

#define COLS    16384
#define THREADS 512
#define VITER   8                 // uint4 per thread per pass (32 elems)
#define NBINS   2048
#define CAP     2048
#define REGCAND 256
#define PIVOT0  0xC0000000u       // key_of(+2.0f), bin-1536 aligned

// Order-preserving float->uint transform (ascending)
__device__ __forceinline__ unsigned key_of(unsigned u) {
    return u ^ (unsigned)(((int)u >> 31) | (int)0x80000000);
}
__device__ __forceinline__ float val_of(unsigned kx) {
    return __uint_as_float(kx ^ (unsigned)((~((int)kx >> 31)) | (int)0x80000000));
}

__global__ void __launch_bounds__(THREADS, 3)
topk_threshold_kernel(const float* __restrict__ x,
                      float* __restrict__ out,
                      const int* __restrict__ kptr)
{
    __shared__ unsigned hist[NBINS];    // 8 KB; reused as tie-bin buffer later
    __shared__ unsigned cand[CAP];      // 8 KB candidate keys (>= pivot)
    __shared__ unsigned wsum[16];
    __shared__ unsigned sh_cnt, sh_bin, sh_krem, sh_bincnt, sh_cnt2, sh_c;
    __shared__ float    sh_thresh;

    const int tid  = threadIdx.x;
    const int lane = tid & 31;
    const int wid  = tid >> 5;
    const size_t row_off = (size_t)blockIdx.x * COLS;
    const uint4* __restrict__ xin = (const uint4*)(x + row_off);
    float4* __restrict__ fin      = (float4*)(x + row_off);
    float4* __restrict__ oout     = (float4*)(out + row_off);

    const unsigned k = kptr ? (unsigned)__ldg(kptr) : 64u;

    #pragma unroll
    for (int b = tid; b < NBINS; b += THREADS) hist[b] = 0u;
    if (tid == 0) sh_cnt = 0u;
    __syncthreads();

    // ---- Pass A: read row, push keys >= pivot into candidate buffer ----
    #pragma unroll
    for (int i = 0; i < VITER; i++) {
        uint4 v = xin[tid + i * THREADS];      // default caching: keep in L2
        #pragma unroll
        for (int j = 0; j < 4; j++) {
            unsigned ky = key_of(((const unsigned*)&v)[j]);
            if (ky >= PIVOT0) {
                unsigned p = atomicAdd(&sh_cnt, 1u);
                if (p < CAP) cand[p] = ky;
            }
        }
    }
    __syncthreads();

    const unsigned ncand = sh_cnt;
    const bool fast = (ncand >= k) && (ncand <= CAP);

    // ---- Histogram (top 11 bits) ----
    if (fast) {
        for (int i = tid; i < (int)ncand; i += THREADS)
            atomicAdd(&hist[cand[i] >> 21], 1u);
    } else {
        // fallback: full histogram via global re-read (exact for any input)
        #pragma unroll
        for (int i = 0; i < VITER; i++) {
            uint4 v = xin[tid + i * THREADS];
            atomicAdd(&hist[key_of(v.x) >> 21], 1u);
            atomicAdd(&hist[key_of(v.y) >> 21], 1u);
            atomicAdd(&hist[key_of(v.z) >> 21], 1u);
            atomicAdd(&hist[key_of(v.w) >> 21], 1u);
        }
    }
    __syncthreads();

    // ---- Bin select: block suffix-sum over 2048 bins (4 bins/thread) ----
    unsigned gs = hist[tid * 4 + 0] + hist[tid * 4 + 1]
                + hist[tid * 4 + 2] + hist[tid * 4 + 3];
    unsigned s = gs;
    #pragma unroll
    for (int off = 1; off < 32; off <<= 1) {
        unsigned v = __shfl_down_sync(0xFFFFFFFFu, s, off);
        if (lane + off < 32) s += v;
    }
    if (lane == 0) wsum[wid] = s;
    __syncthreads();
    unsigned woff = 0;
    #pragma unroll
    for (int w = 0; w < 16; w++) woff += (w > wid) ? wsum[w] : 0u;
    unsigned ssum = s + woff;

    if (ssum >= k && (ssum - gs) < k) {
        unsigned above = ssum - gs;
        int b = 0;
        #pragma unroll
        for (int bb = 3; bb >= 0; bb--) {
            unsigned c = hist[tid * 4 + bb];
            if (above + c >= k) { b = bb; break; }
            above += c;
        }
        sh_bin    = (unsigned)(tid * 4 + b);
        sh_krem   = k - above;
        sh_bincnt = hist[tid * 4 + b];
        sh_cnt2   = 0u;
    }
    __syncthreads();

    const unsigned binp   = sh_bin;
    const unsigned krem1  = sh_krem;
    const unsigned bincnt = sh_bincnt;

    if (bincnt <= CAP) {
        // ---- Compact tie-bin keys (hist region is dead -> reuse as cand2) ----
        unsigned* cand2 = hist;
        if (fast) {
            for (int i = tid; i < (int)ncand; i += THREADS) {
                unsigned ky = cand[i];
                if ((ky >> 21) == binp) {
                    unsigned p = atomicAdd(&sh_cnt2, 1u);
                    cand2[p] = ky;
                }
            }
        } else {
            #pragma unroll
            for (int i = 0; i < VITER; i++) {
                uint4 v = xin[tid + i * THREADS];
                #pragma unroll
                for (int j = 0; j < 4; j++) {
                    unsigned ky = key_of(((const unsigned*)&v)[j]);
                    if ((ky >> 21) == binp) {
                        unsigned p = atomicAdd(&sh_cnt2, 1u);
                        cand2[p] = ky;
                    }
                }
            }
        }
        __syncthreads();

        // ---- Warp 0 refines remaining 21 bits over the tie-bin set ----
        if (wid == 0) {
            const int n = (int)sh_cnt2;
            unsigned krem = krem1;
            unsigned cur  = 0u;
            if (n <= REGCAND) {
                unsigned c[8];
                #pragma unroll
                for (int j = 0; j < 8; j++)
                    c[j] = (lane + 32 * j < n) ? cand2[lane + 32 * j] : 0u;
                for (int bit = 20; bit >= 0; bit--) {
                    unsigned want = (cur << 1) | 1u;
                    unsigned mask = (1u << (21 - bit)) - 1u;
                    unsigned cnt = 0;
                    #pragma unroll
                    for (int j = 0; j < 8; j++)
                        cnt += (((c[j] >> bit) & mask) == want);
                    cnt = __reduce_add_sync(0xFFFFFFFFu, cnt);
                    if (cnt >= krem) cur = want;
                    else { cur = want - 1u; krem -= cnt; }
                }
            } else {
                for (int bit = 20; bit >= 0; bit--) {
                    unsigned want = (cur << 1) | 1u;
                    unsigned mask = (1u << (21 - bit)) - 1u;
                    unsigned cnt = 0;
                    for (int i = lane; i < n; i += 32)
                        cnt += (((cand2[i] >> bit) & mask) == want);
                    cnt = __reduce_add_sync(0xFFFFFFFFu, cnt);
                    if (cnt >= krem) cur = want;
                    else { cur = want - 1u; krem -= cnt; }
                }
            }
            if (lane == 0) sh_thresh = val_of((binp << 21) | cur);
        }
        __syncthreads();
    } else {
        // ---- Pathological tie bin (> CAP ties): bitwise select w/ global re-reads ----
        unsigned krem = krem1;
        unsigned cur  = 0u;
        for (int bit = 20; bit >= 0; bit--) {
            if (tid == 0) sh_c = 0u;
            __syncthreads();
            unsigned want  = (cur << 1) | 1u;
            unsigned fullw = (binp << (21 - bit)) | want;
            unsigned local = 0;
            #pragma unroll
            for (int i = 0; i < VITER; i++) {
                uint4 v = xin[tid + i * THREADS];
                local += ((key_of(v.x) >> bit) == fullw);
                local += ((key_of(v.y) >> bit) == fullw);
                local += ((key_of(v.z) >> bit) == fullw);
                local += ((key_of(v.w) >> bit) == fullw);
            }
            local = __reduce_add_sync(0xFFFFFFFFu, local);
            if (lane == 0) atomicAdd(&sh_c, local);
            __syncthreads();
            unsigned cnt = sh_c;
            if (cnt >= krem) cur = want;
            else { cur = want - 1u; krem -= cnt; }
            __syncthreads();
        }
        if (tid == 0) sh_thresh = val_of((binp << 21) | cur);
        __syncthreads();
    }

    const float t = sh_thresh;

    // ---- Pass B: re-read row (L2-resident), float threshold, stream out ----
    #pragma unroll
    for (int i = 0; i < VITER; i++) {
        float4 v = __ldcs(&fin[tid + i * THREADS]);
        float4 o;
        o.x = (v.x >= t) ? v.x : 0.0f;
        o.y = (v.y >= t) ? v.y : 0.0f;
        o.z = (v.z >= t) ? v.z : 0.0f;
        o.w = (v.w >= t) ? v.w : 0.0f;
        __stcs(&oout[tid + i * THREADS], o);
    }
}

extern "C" void kernel_launch(void* const* d_in, const int* in_sizes, int n_in,
                              void* d_out, int out_size) {
    const float* x  = (const float*)d_in[0];
    const int* kptr = (n_in > 1) ? (const int*)d_in[1] : nullptr;
    const int rows  = in_sizes[0] / COLS;
    topk_threshold_kernel<<<rows, THREADS>>>(x, (float*)d_out, kptr);
}